// round 5
// baseline (speedup 1.0000x reference)
#include <cuda_runtime.h>
#include <math.h>

#define BB 256
#define NN 2048
#define RR 64
#define DD 64
#define TT 8
#define HH 128
#define KD 128

#define GRID    256
#define NTHR    256
#define MCH     16            // nodes per chunk
#define LMAX    256           // max DAG depth supported
#define NGRP    (LMAX * TT)   // (level,type) buckets

// ---------------- global scratch (static: no allocation) ----------------
__device__ unsigned           g_arrive;
__device__ volatile unsigned  g_release;
__device__ int                g_cnt[NGRP];
__device__ int                g_cur[NGRP];
__device__ int                g_off[NGRP + 1];
__device__ int                g_maxl;
__device__ unsigned           g_items[BB * (NN - RR)];   // (b<<11)|node per bucket

__global__ void reset_kernel()
{
    int t = threadIdx.x;
    for (int i = t; i < NGRP; i += NTHR) { g_cnt[i] = 0; g_cur[i] = 0; }
    if (t == 0) { g_arrive = 0; g_release = 0; g_maxl = 0; }
}

__device__ __forceinline__ void grid_barrier(int k)
{
    __syncthreads();
    if (threadIdx.x == 0) {
        __threadfence();                      // publish our STG before arrival
        unsigned old = atomicAdd(&g_arrive, 1u);
        if (old == (unsigned)(k * GRID - 1)) {
            g_release = (unsigned)k;          // volatile store, L2
        } else {
            while (g_release < (unsigned)k) { }
        }
    }
    __syncthreads();
}

// Persistent kernel: prep (levels -> global (level,type) buckets) then
// level-synchronous batched MLP evaluation across all graphs.
__global__ __launch_bounds__(NTHR, 2)
void dag_global_kernel(const float* __restrict__ roots,
                       const float* __restrict__ W1,
                       const float* __restrict__ b1,
                       const float* __restrict__ W2,
                       const float* __restrict__ b2,
                       const int*   __restrict__ g_idx,
                       const int*   __restrict__ g_typ,
                       float*       __restrict__ buf)
{
    const int b    = blockIdx.x;
    const int tid  = threadIdx.x;
    const int lane = tid & 31;
    const int wid  = tid >> 5;

    __shared__ __align__(16) float s_xs[KD * (MCH + 4)];  // X^T [i][m], stride 20
    __shared__ __align__(16) float s_hs[HH * (MCH + 4)];  // H^T [j][m], stride 20

    // prep-phase aliases (prep finishes before GEMM scratch is used)
    unsigned short* s_lvl  = (unsigned short*)s_xs;   // 2048 ush = 4 KB
    unsigned short* s_pidx = (unsigned short*)s_hs;   // 4096 ush = 8 KB

    const int* idxb = g_idx + (size_t)b * (NN * 2);
    const int* typb = g_typ + (size_t)b * NN;

    // ---------------- prep: roots copy + parent staging ----------------
    {
        const float* rs = roots + (size_t)b * (RR * DD);
        float*       bb = buf   + (size_t)b * (NN * DD);
        for (int i = tid; i < RR * DD; i += NTHR) bb[i] = rs[i];
        for (int k = tid; k < NN * 2; k += NTHR)
            s_pidx[k] = (unsigned short)idxb[k];
    }
    __syncthreads();

    // exact levels (serial; parents < n)
    if (tid == 0) {
        for (int n = 0; n < RR; ++n) s_lvl[n] = 0;
        int mx = 0;
        for (int n = RR; n < NN; ++n) {
            int l0 = s_lvl[s_pidx[n * 2 + 0]];
            int l1 = s_lvl[s_pidx[n * 2 + 1]];
            int l  = 1 + (l0 > l1 ? l0 : l1);
            s_lvl[n] = (unsigned short)l;
            if (l > mx) mx = l;
        }
        atomicMax(&g_maxl, mx);
    }
    __syncthreads();

    // global bucket counts
    for (int n = RR + tid; n < NN; n += NTHR)
        atomicAdd(&g_cnt[(int)s_lvl[n] * TT + typb[n]], 1);

    grid_barrier(1);

    // prefix sum (CTA 0) -> offsets & cursors
    if (b == 0 && tid == 0) {
        int acc = 0;
        for (int g = 0; g < NGRP; ++g) {
            g_off[g] = acc;
            g_cur[g] = acc;
            acc += g_cnt[g];
        }
        g_off[NGRP] = acc;
    }
    grid_barrier(2);

    // scatter items into buckets
    for (int n = RR + tid; n < NN; n += NTHR) {
        int key = (int)s_lvl[n] * TT + typb[n];
        int pos = atomicAdd(&g_cur[key], 1);
        g_items[pos] = ((unsigned)b << 11) | (unsigned)n;
    }
    grid_barrier(3);

    const int Lmax = *(volatile int*)&g_maxl;
    int bar = 3;

    const int j128 = tid & 127, ty = tid >> 7;   // GEMM1 mapping
    const int d64  = tid & 63,  q  = tid >> 6;   // GEMM2 mapping

    // ---------------- level-synchronous main loop ----------------
    for (int L = 1; L <= Lmax; ++L) {
        int offs[TT + 1];
        #pragma unroll
        for (int t = 0; t <= TT; ++t) offs[t] = g_off[L * TT + t];
        int cumch[TT + 1];
        cumch[0] = 0;
        #pragma unroll
        for (int t = 0; t < TT; ++t)
            cumch[t + 1] = cumch[t] + (offs[t + 1] - offs[t] + MCH - 1) / MCH;
        const int totch = cumch[TT];

        for (int w = blockIdx.x; w < totch; w += GRID) {
            int t = 0;
            while (w >= cumch[t + 1]) ++t;
            const int goff = offs[t] + (w - cumch[t]) * MCH;
            const int Mc   = min(MCH, offs[t + 1] - goff);

            // ---- gather: warp handles items m = wid, wid+8 ----
            #pragma unroll
            for (int r = 0; r < 2; ++r) {
                int m = wid + r * 8;
                if (m < Mc) {
                    unsigned it = g_items[goff + m];
                    int gb = (int)(it >> 11), gn = (int)(it & 2047);
                    const int* ip = g_idx + ((size_t)gb * NN + gn) * 2;
                    int p0 = ip[0], p1 = ip[1];
                    const float* r0 = buf + ((size_t)gb * NN + p0) * DD;
                    const float* r1 = buf + ((size_t)gb * NN + p1) * DD;
                    s_xs[(lane      ) * (MCH + 4) + m] = __ldcg(r0 + lane);
                    s_xs[(lane + 32 ) * (MCH + 4) + m] = __ldcg(r0 + lane + 32);
                    s_xs[(lane + 64 ) * (MCH + 4) + m] = __ldcg(r1 + lane);
                    s_xs[(lane + 96 ) * (MCH + 4) + m] = __ldcg(r1 + lane + 32);
                }
            }
            __syncthreads();

            // ---- GEMM1 + bias + GELU: thread (j, ty) -> h[j][ty*8..+8) ----
            {
                const float* wp = W1 + (size_t)t * (KD * HH) + j128;
                const float* xp = s_xs + ty * 8;
                float a0=0.f,a1=0.f,a2=0.f,a3=0.f,a4=0.f,a5=0.f,a6=0.f,a7=0.f;
                #pragma unroll 4
                for (int i = 0; i < KD; ++i) {
                    float wv = __ldg(wp + i * HH);
                    float4 x0 = *(const float4*)(xp + i * (MCH + 4));
                    float4 x1 = *(const float4*)(xp + i * (MCH + 4) + 4);
                    a0 += x0.x * wv;  a1 += x0.y * wv;
                    a2 += x0.z * wv;  a3 += x0.w * wv;
                    a4 += x1.x * wv;  a5 += x1.y * wv;
                    a6 += x1.z * wv;  a7 += x1.w * wv;
                }
                const float bv = __ldg(b1 + t * HH + j128);
                float h[8] = {a0,a1,a2,a3,a4,a5,a6,a7};
                #pragma unroll
                for (int k = 0; k < 8; ++k) {
                    float v = h[k] + bv;
                    h[k] = 0.5f * v * (1.0f + erff(v * 0.70710678118654752440f));
                }
                float* hp = s_hs + j128 * (MCH + 4) + ty * 8;
                *(float4*)(hp    ) = make_float4(h[0], h[1], h[2], h[3]);
                *(float4*)(hp + 4) = make_float4(h[4], h[5], h[6], h[7]);
            }
            __syncthreads();

            // ---- GEMM2 + bias + store: thread (d, q) -> out[q*4..+4)][d] ----
            {
                const float* wp = W2 + (size_t)t * (HH * DD) + d64;
                const float* hp = s_hs + q * 4;
                float a0=0.f,a1=0.f,a2=0.f,a3=0.f;
                #pragma unroll 4
                for (int j = 0; j < HH; ++j) {
                    float wv = __ldg(wp + j * DD);
                    float4 h = *(const float4*)(hp + j * (MCH + 4));
                    a0 += h.x * wv;  a1 += h.y * wv;
                    a2 += h.z * wv;  a3 += h.w * wv;
                }
                const float bv = __ldg(b2 + t * DD + d64);
                float o[4] = {a0,a1,a2,a3};
                #pragma unroll
                for (int k = 0; k < 4; ++k) {
                    int m = q * 4 + k;
                    if (m < Mc) {
                        unsigned it = g_items[goff + m];
                        int gb = (int)(it >> 11), gn = (int)(it & 2047);
                        buf[((size_t)gb * NN + gn) * DD + d64] = o[k] + bv;
                    }
                }
            }
            __syncthreads();   // protect s_xs/s_hs before next chunk
        }

        grid_barrier(++bar);   // level complete across all CTAs
    }
}

extern "C" void kernel_launch(void* const* d_in, const int* in_sizes, int n_in,
                              void* d_out, int out_size)
{
    const float* roots = (const float*)d_in[0];
    const float* W1    = (const float*)d_in[1];
    const float* b1    = (const float*)d_in[2];
    const float* W2    = (const float*)d_in[3];
    const float* b2    = (const float*)d_in[4];
    const int*   idx   = (const int*)  d_in[5];
    const int*   typ   = (const int*)  d_in[6];
    float*       out   = (float*)d_out;

    reset_kernel<<<1, NTHR>>>();
    dag_global_kernel<<<GRID, NTHR>>>(roots, W1, b1, W2, b2, idx, typ, out);
}

// round 6
// speedup vs baseline: 1.1632x; 1.1632x over previous
#include <cuda_runtime.h>
#include <math.h>

#define BB 256
#define NN 2048
#define RR 64
#define DD 64
#define TT 8
#define HH 128
#define KD 128

#define GRID    256
#define NTHR    256
#define MCH     32            // nodes per chunk
#define MS      (MCH + 4)     // smem row stride (36 floats, 16B-multiple)
#define LMAX    256
#define NGRP    (LMAX * TT)

// ---------------- global scratch (static: no allocation) ----------------
__device__ unsigned           g_arrive;
__device__ volatile unsigned  g_release;
__device__ int                g_cnt[NGRP];
__device__ int                g_cur[NGRP];
__device__ int                g_off[NGRP + 1];
__device__ int                g_maxl;
__device__ unsigned           g_items[BB * (NN - RR)];   // (b<<11)|node

__global__ void reset_kernel()
{
    int t = threadIdx.x;
    for (int i = t; i < NGRP; i += NTHR) { g_cnt[i] = 0; g_cur[i] = 0; }
    if (t == 0) { g_arrive = 0; g_release = 0; g_maxl = 0; }
}

__device__ __forceinline__ void grid_barrier(int k)
{
    __syncthreads();
    if (threadIdx.x == 0) {
        __threadfence();
        unsigned old = atomicAdd(&g_arrive, 1u);
        if (old == (unsigned)(k * GRID - 1)) {
            g_release = (unsigned)k;
        } else {
            while (g_release < (unsigned)k) { }
        }
    }
    __syncthreads();
}

__global__ __launch_bounds__(NTHR, 2)
void dag_global_kernel(const float* __restrict__ roots,
                       const float* __restrict__ W1,
                       const float* __restrict__ b1,
                       const float* __restrict__ W2,
                       const float* __restrict__ b2,
                       const int*   __restrict__ g_idx,
                       const int*   __restrict__ g_typ,
                       float*       __restrict__ buf)
{
    const int b    = blockIdx.x;
    const int tid  = threadIdx.x;
    const int lane = tid & 31;
    const int wid  = tid >> 5;

    __shared__ __align__(16) float s_xs[KD * MS];  // X^T [i][m]
    __shared__ __align__(16) float s_hs[HH * MS];  // H^T [j][m]

    // prep-phase aliases (dead before GEMM phase starts)
    unsigned short* s_lvl  = (unsigned short*)s_xs;   // 4 KB
    unsigned short* s_pidx = (unsigned short*)s_hs;   // 8 KB

    const int* idxb = g_idx + (size_t)b * (NN * 2);
    const int* typb = g_typ + (size_t)b * NN;

    // ---------------- prep: roots copy + parent staging ----------------
    {
        const float* rs = roots + (size_t)b * (RR * DD);
        float*       bb = buf   + (size_t)b * (NN * DD);
        for (int i = tid; i < RR * DD; i += NTHR) bb[i] = rs[i];
        for (int k = tid; k < NN * 2; k += NTHR)
            s_pidx[k] = (unsigned short)idxb[k];
    }
    __syncthreads();

    // exact levels (serial; parents < n)
    if (tid == 0) {
        for (int n = 0; n < RR; ++n) s_lvl[n] = 0;
        int mx = 0;
        for (int n = RR; n < NN; ++n) {
            int l0 = s_lvl[s_pidx[n * 2 + 0]];
            int l1 = s_lvl[s_pidx[n * 2 + 1]];
            int l  = 1 + (l0 > l1 ? l0 : l1);
            s_lvl[n] = (unsigned short)l;
            if (l > mx) mx = l;
        }
        atomicMax(&g_maxl, mx);
    }
    __syncthreads();

    for (int n = RR + tid; n < NN; n += NTHR)
        atomicAdd(&g_cnt[(int)s_lvl[n] * TT + typb[n]], 1);

    grid_barrier(1);

    if (b == 0 && tid == 0) {
        int acc = 0;
        for (int g = 0; g < NGRP; ++g) {
            g_off[g] = acc;
            g_cur[g] = acc;
            acc += g_cnt[g];
        }
        g_off[NGRP] = acc;
    }
    grid_barrier(2);

    for (int n = RR + tid; n < NN; n += NTHR) {
        int key = (int)s_lvl[n] * TT + typb[n];
        int pos = atomicAdd(&g_cur[key], 1);
        g_items[pos] = ((unsigned)b << 11) | (unsigned)n;
    }
    grid_barrier(3);

    const int Lmax = *(volatile int*)&g_maxl;
    int bar = 3;

    // type affinity: this CTA only ever touches weights of type tmy
    const int tmy = b >> 5;           // 8 types x 32 CTAs
    const int ci  = b & 31;           // index within the type's CTA team

    const float* w1t = W1 + (size_t)tmy * (KD * HH);
    const float* w2t = W2 + (size_t)tmy * (HH * DD);
    const float  bv1 = __ldg(b1 + tmy * HH + (tid & 127));
    const float  bv2 = __ldg(b2 + tmy * DD + (tid & 63));

    const int j128 = tid & 127, mh = tid >> 7;   // GEMM1 mapping
    const int d64  = tid & 63,  mq = tid >> 6;   // GEMM2 mapping

    // ---------------- level-synchronous main loop ----------------
    for (int L = 1; L <= Lmax; ++L) {
        const int lo  = g_off[L * TT + tmy];
        const int hi  = g_off[L * TT + tmy + 1];
        const int nch = (hi - lo + MCH - 1) / MCH;

        for (int c = ci; c < nch; c += 32) {
            const int goff = lo + c * MCH;
            const int Mc   = min(MCH, hi - goff);

            // ---- gather: warp w handles items m = w, w+8, w+16, w+24 ----
            #pragma unroll
            for (int r = 0; r < 4; ++r) {
                int m = wid + r * 8;
                if (m < Mc) {
                    unsigned it = g_items[goff + m];
                    int gb = (int)(it >> 11), gn = (int)(it & 2047);
                    const int* ip = g_idx + ((size_t)gb * NN + gn) * 2;
                    int p0 = ip[0], p1 = ip[1];
                    const float* r0 = buf + ((size_t)gb * NN + p0) * DD;
                    const float* r1 = buf + ((size_t)gb * NN + p1) * DD;
                    s_xs[(lane      ) * MS + m] = __ldcg(r0 + lane);
                    s_xs[(lane + 32 ) * MS + m] = __ldcg(r0 + lane + 32);
                    s_xs[(lane + 64 ) * MS + m] = __ldcg(r1 + lane);
                    s_xs[(lane + 96 ) * MS + m] = __ldcg(r1 + lane + 32);
                }
            }
            __syncthreads();

            // ---- GEMM1 + bias + GELU: thread (j, mh) -> h[j][mh*16..+16) ----
            {
                const float* wp = w1t + j128;
                const float* xp = s_xs + mh * 16;
                float a[16];
                #pragma unroll
                for (int k = 0; k < 16; ++k) a[k] = 0.f;
                #pragma unroll 2
                for (int i = 0; i < KD; ++i) {
                    float wv = __ldg(wp + i * HH);
                    float4 x0 = *(const float4*)(xp + i * MS     );
                    float4 x1 = *(const float4*)(xp + i * MS + 4 );
                    float4 x2 = *(const float4*)(xp + i * MS + 8 );
                    float4 x3 = *(const float4*)(xp + i * MS + 12);
                    a[0]  += x0.x * wv;  a[1]  += x0.y * wv;
                    a[2]  += x0.z * wv;  a[3]  += x0.w * wv;
                    a[4]  += x1.x * wv;  a[5]  += x1.y * wv;
                    a[6]  += x1.z * wv;  a[7]  += x1.w * wv;
                    a[8]  += x2.x * wv;  a[9]  += x2.y * wv;
                    a[10] += x2.z * wv;  a[11] += x2.w * wv;
                    a[12] += x3.x * wv;  a[13] += x3.y * wv;
                    a[14] += x3.z * wv;  a[15] += x3.w * wv;
                }
                #pragma unroll
                for (int k = 0; k < 16; ++k) {
                    float v = a[k] + bv1;
                    a[k] = 0.5f * v * (1.0f + erff(v * 0.70710678118654752440f));
                }
                float* hp = s_hs + j128 * MS + mh * 16;
                *(float4*)(hp     ) = make_float4(a[0],  a[1],  a[2],  a[3]);
                *(float4*)(hp + 4 ) = make_float4(a[4],  a[5],  a[6],  a[7]);
                *(float4*)(hp + 8 ) = make_float4(a[8],  a[9],  a[10], a[11]);
                *(float4*)(hp + 12) = make_float4(a[12], a[13], a[14], a[15]);
            }
            __syncthreads();

            // ---- GEMM2 + bias + store: thread (d, mq) -> out[mq*8..+8)][d] ----
            {
                const float* wp = w2t + d64;
                const float* hp = s_hs + mq * 8;
                float a0=0.f,a1=0.f,a2=0.f,a3=0.f,a4=0.f,a5=0.f,a6=0.f,a7=0.f;
                #pragma unroll 4
                for (int j = 0; j < HH; ++j) {
                    float wv = __ldg(wp + j * DD);
                    float4 h0 = *(const float4*)(hp + j * MS    );
                    float4 h1 = *(const float4*)(hp + j * MS + 4);
                    a0 += h0.x * wv;  a1 += h0.y * wv;
                    a2 += h0.z * wv;  a3 += h0.w * wv;
                    a4 += h1.x * wv;  a5 += h1.y * wv;
                    a6 += h1.z * wv;  a7 += h1.w * wv;
                }
                float o[8] = {a0,a1,a2,a3,a4,a5,a6,a7};
                #pragma unroll
                for (int k = 0; k < 8; ++k) {
                    int m = mq * 8 + k;
                    if (m < Mc) {
                        unsigned it = g_items[goff + m];
                        int gb = (int)(it >> 11), gn = (int)(it & 2047);
                        buf[((size_t)gb * NN + gn) * DD + d64] = o[k] + bv2;
                    }
                }
            }
            __syncthreads();
        }

        grid_barrier(++bar);
    }
}

extern "C" void kernel_launch(void* const* d_in, const int* in_sizes, int n_in,
                              void* d_out, int out_size)
{
    const float* roots = (const float*)d_in[0];
    const float* W1    = (const float*)d_in[1];
    const float* b1    = (const float*)d_in[2];
    const float* W2    = (const float*)d_in[3];
    const float* b2    = (const float*)d_in[4];
    const int*   idx   = (const int*)  d_in[5];
    const int*   typ   = (const int*)  d_in[6];
    float*       out   = (float*)d_out;

    reset_kernel<<<1, NTHR>>>();
    dag_global_kernel<<<GRID, NTHR>>>(roots, W1, b1, W2, b2, idx, typ, out);
}

// round 9
// speedup vs baseline: 1.2464x; 1.0716x over previous
#include <cuda_runtime.h>
#include <math.h>

#define BB 256
#define NN 2048
#define RR 64
#define DD 64
#define TT 8
#define HH 128
#define KD 128

#define GRID    256
#define NTHR    256
#define MCH     32            // nodes per chunk
#define MS      (MCH + 4)     // smem row stride
#define LMAX    256
#define NGRP    (LMAX * TT)   // bucket key = t*LMAX + L

// ---------------- global scratch (static: no allocation) ----------------
__device__ unsigned           g_arrive;
__device__ volatile unsigned  g_release;
__device__ int                g_cnt[NGRP];
__device__ int                g_cur[NGRP];             // scatter cursors
__device__ int                g_off[NGRP + 1];
__device__ int                g_ccum[TT * (LMAX + 1)]; // per-type chunk prefix over levels
__device__ int                g_tcur[TT];              // per-type team chunk cursor
__device__ int                g_maxl;
__device__ unsigned long long g_items[BB * (NN - RR)]; // (b<<33)|(n<<22)|(p0<<11)|p1
__device__ unsigned           g_flag[BB * NN];         // node-done flags

__global__ void reset_kernel()
{
    int gt = blockIdx.x * NTHR + threadIdx.x;
    for (int i = gt; i < BB * NN; i += GRID * NTHR) g_flag[i] = 0u;
    for (int i = gt; i < NGRP;   i += GRID * NTHR) g_cnt[i] = 0;
    if (gt < TT) g_tcur[gt] = 0;
    if (gt == 0) { g_arrive = 0; g_release = 0; g_maxl = 0; }
}

__device__ __forceinline__ void grid_barrier(int k)
{
    __syncthreads();
    if (threadIdx.x == 0) {
        __threadfence();   // release side
        unsigned old = atomicAdd(&g_arrive, 1u);
        if (old == (unsigned)(k * GRID - 1)) {
            g_release = (unsigned)k;
        } else {
            while (g_release < (unsigned)k) { }
        }
        __threadfence();   // acquire side
    }
    __syncthreads();
}

// STRONG scoped flag ops: these are the synchronizing operations the PTX
// memory model requires (weak .cg ops never pair with fences).
__device__ __forceinline__ unsigned ld_acq_u32(const unsigned* p)
{
    unsigned v;
    asm volatile("ld.acquire.gpu.global.u32 %0, [%1];"
                 : "=r"(v) : "l"(p) : "memory");
    return v;
}
__device__ __forceinline__ void st_rel_u32(unsigned* p, unsigned v)
{
    asm volatile("st.release.gpu.global.u32 [%0], %1;"
                 :: "l"(p), "r"(v) : "memory");
}

__global__ __launch_bounds__(NTHR, 2)
void dag_global_kernel(const float* __restrict__ roots,
                       const float* __restrict__ W1,
                       const float* __restrict__ b1,
                       const float* __restrict__ W2,
                       const float* __restrict__ b2,
                       const int*   __restrict__ g_idx,
                       const int*   __restrict__ g_typ,
                       float*       __restrict__ buf)
{
    const int b    = blockIdx.x;
    const int tid  = threadIdx.x;
    const int lane = tid & 31;
    const int wid  = tid >> 5;

    __shared__ __align__(16) float s_xs[KD * MS];
    __shared__ __align__(16) float s_hs[HH * MS];
    __shared__ int s_ccum[LMAX + 1];
    __shared__ int s_k;

    unsigned short* s_lvl  = (unsigned short*)s_xs;   // prep aliases
    unsigned short* s_pidx = (unsigned short*)s_hs;

    const int* idxb = g_idx + (size_t)b * (NN * 2);
    const int* typb = g_typ + (size_t)b * NN;

    // ---------------- prep ----------------
    {
        const float* rs = roots + (size_t)b * (RR * DD);
        float*       bb = buf   + (size_t)b * (NN * DD);
        for (int i = tid; i < RR * DD; i += NTHR) bb[i] = rs[i];
        for (int k = tid; k < NN * 2; k += NTHR)
            s_pidx[k] = (unsigned short)idxb[k];
        // root flags (made globally visible by grid_barrier(3)'s fences)
        for (int n = tid; n < RR; n += NTHR)
            g_flag[b * NN + n] = 1u;
    }
    __syncthreads();

    if (tid == 0) {
        for (int n = 0; n < RR; ++n) s_lvl[n] = 0;
        int mx = 0;
        for (int n = RR; n < NN; ++n) {
            int l0 = s_lvl[s_pidx[n * 2 + 0]];
            int l1 = s_lvl[s_pidx[n * 2 + 1]];
            int l  = 1 + (l0 > l1 ? l0 : l1);
            s_lvl[n] = (unsigned short)l;
            if (l > mx) mx = l;
        }
        atomicMax(&g_maxl, mx);
    }
    __syncthreads();

    for (int n = RR + tid; n < NN; n += NTHR)
        atomicAdd(&g_cnt[typb[n] * LMAX + (int)s_lvl[n]], 1);

    grid_barrier(1);

    // CTA0: per-type prefix sums (8 threads, one per type)
    if (b == 0) {
        __shared__ int s_ttot[TT];
        if (tid < TT) {
            int tot = 0;
            for (int L = 0; L < LMAX; ++L) tot += g_cnt[tid * LMAX + L];
            s_ttot[tid] = tot;
        }
        __syncthreads();
        if (tid < TT) {
            int base = 0;
            for (int t = 0; t < tid; ++t) base += s_ttot[t];
            int acc = base;
            for (int L = 0; L < LMAX; ++L) {
                g_off[tid * LMAX + L] = acc;
                g_cur[tid * LMAX + L] = acc;
                acc += g_cnt[tid * LMAX + L];
            }
            if (tid == TT - 1) g_off[NGRP] = acc;
            int cacc = 0;
            g_ccum[tid * (LMAX + 1)] = 0;
            for (int L = 1; L <= LMAX; ++L) {
                cacc += (g_cnt[tid * LMAX + L] + MCH - 1) / MCH;
                g_ccum[tid * (LMAX + 1) + L] = cacc;
            }
        }
    }
    grid_barrier(2);

    // scatter items (64-bit packed with parent indices)
    for (int n = RR + tid; n < NN; n += NTHR) {
        int key = typb[n] * LMAX + (int)s_lvl[n];
        int pos = atomicAdd(&g_cur[key], 1);
        unsigned long long p0 = s_pidx[n * 2 + 0];
        unsigned long long p1 = s_pidx[n * 2 + 1];
        g_items[pos] = ((unsigned long long)b << 33)
                     | ((unsigned long long)n << 22) | (p0 << 11) | p1;
    }
    grid_barrier(3);

    // ---------------- dataflow main loop ----------------
    const int tmy = b >> 5;
    const int Lmx = *(volatile int*)&g_maxl;

    for (int i = tid; i <= LMAX; i += NTHR) s_ccum[i] = g_ccum[tmy * (LMAX + 1) + i];
    __syncthreads();
    const int total = s_ccum[Lmx];

    const float* w1t = W1 + (size_t)tmy * (KD * HH);
    const float* w2t = W2 + (size_t)tmy * (HH * DD);
    const float  bv1 = __ldg(b1 + tmy * HH + (tid & 127));
    const float  bv2 = __ldg(b2 + tmy * DD + (tid & 63));

    const int j128 = tid & 127, mh = tid >> 7;
    const int d64  = tid & 63,  mq = tid >> 6;

    while (true) {
        if (tid == 0) s_k = atomicAdd(&g_tcur[tmy], 1);
        __syncthreads();
        const int k = s_k;
        if (k >= total) break;

        // locate (level, chunk-in-level)
        int loL = 1, hiL = Lmx;
        while (loL < hiL) { int mid = (loL + hiL) >> 1;
                            if (s_ccum[mid] > k) hiL = mid; else loL = mid + 1; }
        const int L    = loL;
        const int cidx = k - s_ccum[L - 1];
        const int base = g_off[tmy * LMAX + L];
        const int cnt  = g_off[tmy * LMAX + L + 1] - base;
        const int goff = base + cidx * MCH;
        const int Mc   = min(MCH, cnt - cidx * MCH);

        // ---- poll parents ready (strong acquire loads) ----
        unsigned long long itv[4];
        #pragma unroll
        for (int r = 0; r < 4; ++r) {
            int m = wid + r * 8;
            itv[r] = 0;
            if (m < Mc) {
                itv[r] = g_items[goff + m];
                unsigned gb = (unsigned)(itv[r] >> 33);
                unsigned p0 = (unsigned)(itv[r] >> 11) & 2047u;
                unsigned p1 = (unsigned)itv[r] & 2047u;
                const unsigned* f0 = &g_flag[gb * NN + p0];
                const unsigned* f1 = &g_flag[gb * NN + p1];
                while (ld_acq_u32(f0) == 0u) { }
                while (ld_acq_u32(f1) == 0u) { }
            }
        }
        __threadfence();   // belt-and-suspenders acquire

        // ---- gather ----
        #pragma unroll
        for (int r = 0; r < 4; ++r) {
            int m = wid + r * 8;
            if (m < Mc) {
                unsigned gb = (unsigned)(itv[r] >> 33);
                unsigned p0 = (unsigned)(itv[r] >> 11) & 2047u;
                unsigned p1 = (unsigned)itv[r] & 2047u;
                const float* r0 = buf + ((size_t)gb * NN + p0) * DD;
                const float* r1 = buf + ((size_t)gb * NN + p1) * DD;
                s_xs[(lane      ) * MS + m] = __ldcg(r0 + lane);
                s_xs[(lane + 32 ) * MS + m] = __ldcg(r0 + lane + 32);
                s_xs[(lane + 64 ) * MS + m] = __ldcg(r1 + lane);
                s_xs[(lane + 96 ) * MS + m] = __ldcg(r1 + lane + 32);
            }
        }
        __syncthreads();

        // ---- GEMM1 + bias + GELU ----
        {
            const float* wp = w1t + j128;
            const float* xp = s_xs + mh * 16;
            float a[16];
            #pragma unroll
            for (int q = 0; q < 16; ++q) a[q] = 0.f;
            #pragma unroll 2
            for (int i = 0; i < KD; ++i) {
                float wv = __ldg(wp + i * HH);
                float4 x0 = *(const float4*)(xp + i * MS     );
                float4 x1 = *(const float4*)(xp + i * MS + 4 );
                float4 x2 = *(const float4*)(xp + i * MS + 8 );
                float4 x3 = *(const float4*)(xp + i * MS + 12);
                a[0]  += x0.x * wv;  a[1]  += x0.y * wv;
                a[2]  += x0.z * wv;  a[3]  += x0.w * wv;
                a[4]  += x1.x * wv;  a[5]  += x1.y * wv;
                a[6]  += x1.z * wv;  a[7]  += x1.w * wv;
                a[8]  += x2.x * wv;  a[9]  += x2.y * wv;
                a[10] += x2.z * wv;  a[11] += x2.w * wv;
                a[12] += x3.x * wv;  a[13] += x3.y * wv;
                a[14] += x3.z * wv;  a[15] += x3.w * wv;
            }
            #pragma unroll
            for (int q = 0; q < 16; ++q) {
                float v = a[q] + bv1;
                a[q] = 0.5f * v * (1.0f + erff(v * 0.70710678118654752440f));
            }
            float* hp = s_hs + j128 * MS + mh * 16;
            *(float4*)(hp     ) = make_float4(a[0],  a[1],  a[2],  a[3]);
            *(float4*)(hp + 4 ) = make_float4(a[4],  a[5],  a[6],  a[7]);
            *(float4*)(hp + 8 ) = make_float4(a[8],  a[9],  a[10], a[11]);
            *(float4*)(hp + 12) = make_float4(a[12], a[13], a[14], a[15]);
        }
        __syncthreads();

        // ---- GEMM2 + bias + store ----
        {
            const float* wp = w2t + d64;
            const float* hp = s_hs + mq * 8;
            float a0=0.f,a1=0.f,a2=0.f,a3=0.f,a4=0.f,a5=0.f,a6=0.f,a7=0.f;
            #pragma unroll 4
            for (int j = 0; j < HH; ++j) {
                float wv = __ldg(wp + j * DD);
                float4 h0 = *(const float4*)(hp + j * MS    );
                float4 h1 = *(const float4*)(hp + j * MS + 4);
                a0 += h0.x * wv;  a1 += h0.y * wv;
                a2 += h0.z * wv;  a3 += h0.w * wv;
                a4 += h1.x * wv;  a5 += h1.y * wv;
                a6 += h1.z * wv;  a7 += h1.w * wv;
            }
            float o[8] = {a0,a1,a2,a3,a4,a5,a6,a7};
            #pragma unroll
            for (int q = 0; q < 8; ++q) {
                int m = mq * 8 + q;
                if (m < Mc) {
                    unsigned long long it = g_items[goff + m];
                    unsigned gb = (unsigned)(it >> 33);
                    unsigned gn = (unsigned)(it >> 22) & 2047u;
                    buf[((size_t)gb * NN + gn) * DD + d64] = o[q] + bv2;
                }
            }
        }

        // ---- publish: bar (folds all CTA stores into HB) -> fence -> release-store
        __syncthreads();
        __threadfence();
        if (tid < Mc) {
            unsigned long long it = g_items[goff + tid];
            unsigned gb = (unsigned)(it >> 33);
            unsigned gn = (unsigned)(it >> 22) & 2047u;
            st_rel_u32(&g_flag[gb * NN + gn], 1u);
        }
        __syncthreads();    // protect s_xs/s_hs/s_k reuse
    }
}

extern "C" void kernel_launch(void* const* d_in, const int* in_sizes, int n_in,
                              void* d_out, int out_size)
{
    const float* roots = (const float*)d_in[0];
    const float* W1    = (const float*)d_in[1];
    const float* b1    = (const float*)d_in[2];
    const float* W2    = (const float*)d_in[3];
    const float* b2    = (const float*)d_in[4];
    const int*   idx   = (const int*)  d_in[5];
    const int*   typ   = (const int*)  d_in[6];
    float*       out   = (float*)d_out;

    reset_kernel<<<GRID, NTHR>>>();
    dag_global_kernel<<<GRID, NTHR>>>(roots, W1, b1, W2, b2, idx, typ, out);
}